// round 14
// baseline (speedup 1.0000x reference)
#include <cuda_runtime.h>
#include <cstdint>
#include <cmath>

// ---------------------------------------------------------------------------
// Head_55671366091048 (sm_103a), warp-specialized tcgen05, 256x256 tiles.
//   Wc = rna(W)
//   q = rna(x) Wqc^T ; k = rna(y) Wkc^T ; vT = (rna(y) Wvc^T)^T  (fused z=3)
//   a = mask(q k^T) * d^-1/2    (strict lower; 256x256 blocks, skip bn>bm)
//   part[c] = a[:, c*2048:(c+1)*2048] vT^T  (split-K, balanced 160 CTAs)
//   out = sum_c part[c]                      (fixed-order reduce)
//
// Round-13 bug fixed: MODE-4 A producer copied only 64 B of each 128 B tile
// row (cols 16-31 garbage). Now loads/stores full 8 x float4 per row.
// 9 warps: 0-7 produce (cp.async / LDG+rna+STS), warp 8 MMAs.
// S=3 x 64KB stages, TMEM 512 cols, 1 CTA/SM.
// compute_103 PTX pass gets a naive fallback (never runs on HW).
// ---------------------------------------------------------------------------

#if defined(__CUDA_ARCH__) && defined(__CUDA_ARCH_FEAT_SM103_ALL)
#define USE_TCGEN05 1
#else
#define USE_TCGEN05 0
#endif

namespace {
constexpr int kNX = 8192;
constexpr int kNY = 8192;
constexpr int kC  = 2048;
constexpr int kD  = 512;

constexpr int BMC = 256;                 // CTA rows (2 x 128 MMA m-blocks)
constexpr int BNC = 256;                 // CTA cols
constexpr int KT  = 32;                  // K per smem tile (128B rows)
constexpr int SS  = 3;                   // stages
constexpr int ABYTES = BMC * 128;        // 32 KB
constexpr int BBYTES = BNC * 128;        // 32 KB
constexpr int STB = ABYTES + BBYTES;     // 64 KB
constexpr int MBAR_OFF = 64;             // full[s] @ +16s, done[s] @ +16s+8
constexpr int DATA_OFF = 1024;
constexpr int SMEM_SZ = DATA_OFF + SS * STB;   // 197632 B -> 1 CTA/SM

constexpr int NTHREADS = 288;            // 8 producer warps + 1 MMA warp
constexpr int KCHUNK = 2048;             // split-K chunk (stage 3)
constexpr size_t OUT_ELEMS = (size_t)kNX * kD;

constexpr uint64_t DESC_BASE =
    (uint64_t(2) << 61) | (uint64_t(1) << 46) | (uint64_t(64) << 32) |
    (uint64_t(1) << 16);

// idesc kind::tf32: dtype F32, a/b TF32, N=256, M=128 per dispatch
constexpr uint32_t IDESC =
    (1u << 4) | (2u << 7) | (2u << 10) | ((BNC / 8) << 17) | (8u << 24);
}  // namespace

__device__ float g_wqc[(size_t)kD * kC];
__device__ float g_wkc[(size_t)kD * kC];
__device__ float g_wvc[(size_t)kD * kC];
__device__ float g_q[(size_t)kNX * kD];
__device__ float g_k[(size_t)kNY * kD];
__device__ float g_vT[(size_t)kD * kNY];
__device__ float g_a[(size_t)kNX * kNY];
__device__ float g_part[4][OUT_ELEMS];   // split-K partials

// ---------------------------------------------------------------------------
__device__ __forceinline__ uint32_t smem_u32(const void* p) {
  uint32_t a;
  asm("{ .reg .u64 t; cvta.to.shared.u64 t, %1; cvt.u32.u64 %0, t; }"
      : "=r"(a) : "l"(p));
  return a;
}
__device__ __forceinline__ float tf32r(float f) {
  uint32_t u;
  asm("cvt.rna.tf32.f32 %0, %1;" : "=r"(u) : "f"(f));
  return __uint_as_float(u);
}
__device__ __forceinline__ float4 tf32r4(float4 v) {
  return make_float4(tf32r(v.x), tf32r(v.y), tf32r(v.z), tf32r(v.w));
}

__global__ void cvt_kernel(const float* s0, float* d0, const float* s1,
                           float* d1, const float* s2, float* d2, int n) {
  const int z = blockIdx.z;
  const float* s = (z == 0) ? s0 : (z == 1) ? s1 : s2;
  float* d = (z == 0) ? d0 : (z == 1) ? d1 : d2;
  int i = (blockIdx.x * blockDim.x + threadIdx.x) * 4;
  const int stride = gridDim.x * blockDim.x * 4;
  for (; i < n; i += stride) *(float4*)(d + i) = tf32r4(*(const float4*)(s + i));
}

// out = sum over valid chunks of part[c]; nch(row) = row/2048 + 1 (1..4)
__global__ void reduce_kernel(const float* __restrict__ part,
                              float* __restrict__ out) {
  const size_t i4 = ((size_t)blockIdx.x * blockDim.x + threadIdx.x) * 4;
  if (i4 >= OUT_ELEMS) return;
  const int row = (int)(i4 / kD);
  const int nch = row / KCHUNK + 1;
  float4 s = *(const float4*)(part + i4);
  for (int c = 1; c < nch; ++c) {
    const float4 p = *(const float4*)(part + (size_t)c * OUT_ELEMS + i4);
    s.x += p.x; s.y += p.y; s.z += p.z; s.w += p.w;
  }
  *(float4*)(out + i4) = s;
}

#if USE_TCGEN05
__device__ __forceinline__ void mbar_init(uint32_t addr, uint32_t cnt) {
  asm volatile("mbarrier.init.shared.b64 [%0], %1;" :: "r"(addr), "r"(cnt)
               : "memory");
}
__device__ __forceinline__ void mbar_inval(uint32_t addr) {
  asm volatile("mbarrier.inval.shared.b64 [%0];" :: "r"(addr) : "memory");
}
__device__ __forceinline__ void mbar_arrive(uint32_t addr) {
  asm volatile("mbarrier.arrive.shared.b64 _, [%0];" :: "r"(addr) : "memory");
}
__device__ __forceinline__ void mbar_wait(uint32_t addr, uint32_t parity) {
  uint32_t done;
  asm volatile(
      "{\n\t.reg .pred p;\n\t"
      "mbarrier.try_wait.parity.acquire.cta.shared::cta.b64 p, [%1], %2;\n\t"
      "selp.b32 %0, 1, 0, p;\n\t}"
      : "=r"(done) : "r"(addr), "r"(parity) : "memory");
  if (!done) {
    asm volatile(
        "{\n\t.reg .pred P1;\n\t"
        "WL_%=:\n\t"
        "mbarrier.try_wait.parity.acquire.cta.shared::cta.b64 P1, [%0], %1, 0x989680;\n\t"
        "@P1 bra.uni WD_%=;\n\t"
        "bra.uni WL_%=;\n\t"
        "WD_%=:\n\t}"
        :: "r"(addr), "r"(parity) : "memory");
  }
}
__device__ __forceinline__ void tmem_alloc(uint32_t smem_dst, uint32_t ncols) {
  asm volatile(
      "tcgen05.alloc.cta_group::1.sync.aligned.shared::cta.b32 [%0], %1;"
      :: "r"(smem_dst), "r"(ncols) : "memory");
}
__device__ __forceinline__ void tmem_relinq() {
  asm volatile("tcgen05.relinquish_alloc_permit.cta_group::1.sync.aligned;");
}
__device__ __forceinline__ void tmem_dealloc(uint32_t tmem, uint32_t ncols) {
  asm volatile("tcgen05.dealloc.cta_group::1.sync.aligned.b32 %0, %1;"
               :: "r"(tmem), "r"(ncols));
}
__device__ __forceinline__ void mma_tf32(uint32_t d, uint64_t ad, uint64_t bd,
                                         uint32_t idesc, bool accum) {
  uint32_t en = accum ? 1u : 0u;
  asm volatile(
      "{\n\t.reg .pred p;\n\t"
      "setp.ne.u32 p, %4, 0;\n\t"
      "tcgen05.mma.cta_group::1.kind::tf32 [%0], %1, %2, %3, {%5,%5,%5,%5}, p;\n\t}"
      :: "r"(d), "l"(ad), "l"(bd), "r"(idesc), "r"(en), "r"(0u) : "memory");
}
__device__ __forceinline__ void mma_commit(uint32_t mbar) {
  asm volatile(
      "tcgen05.commit.cta_group::1.mbarrier::arrive::one.shared::cluster.b64 [%0];"
      :: "r"(mbar) : "memory");
}
__device__ __forceinline__ void ldtm_x32(uint32_t* r, uint32_t addr) {
  asm volatile(
      "tcgen05.ld.sync.aligned.32x32b.x32.b32 "
      "{%0,%1,%2,%3,%4,%5,%6,%7,%8,%9,%10,%11,%12,%13,%14,%15,"
      "%16,%17,%18,%19,%20,%21,%22,%23,%24,%25,%26,%27,%28,%29,%30,%31}, [%32];"
      : "=r"(r[0]), "=r"(r[1]), "=r"(r[2]), "=r"(r[3]), "=r"(r[4]), "=r"(r[5]),
        "=r"(r[6]), "=r"(r[7]), "=r"(r[8]), "=r"(r[9]), "=r"(r[10]),
        "=r"(r[11]), "=r"(r[12]), "=r"(r[13]), "=r"(r[14]), "=r"(r[15]),
        "=r"(r[16]), "=r"(r[17]), "=r"(r[18]), "=r"(r[19]), "=r"(r[20]),
        "=r"(r[21]), "=r"(r[22]), "=r"(r[23]), "=r"(r[24]), "=r"(r[25]),
        "=r"(r[26]), "=r"(r[27]), "=r"(r[28]), "=r"(r[29]), "=r"(r[30]),
        "=r"(r[31])
      : "r"(addr));
}
__device__ __forceinline__ void cp16(uint32_t dst, const void* src) {
  asm volatile("cp.async.cg.shared.global [%0], [%1], 16;"
               :: "r"(dst), "l"(src) : "memory");
}
__device__ __forceinline__ void cp_arrive_noinc(uint32_t mbar) {
  asm volatile("cp.async.mbarrier.arrive.noinc.shared.b64 [%0];"
               :: "r"(mbar) : "memory");
}
#endif  // USE_TCGEN05

#define SWZ(o) ((o) ^ (((o) >> 3) & 0x70))

// ---------------------------------------------------------------------------
// Warp-specialized NT GEMM, 256x256 CTA tile, TMEM 512 cols.
// MODE 2: skip bn>bm (256-blocks); mask+scale epilogue (tf32-rounded).
// MODE 4: fused projections; A in-producer (LDG->rna->STS, FULL 128B row);
//         z=0 q, z=1 k, z=2 vT (transposed store), tf32-rounded.
// MODE 5: stage-3 split-K: chunk z covers K [z*2048, min(Keff,(z+1)*2048));
//         Keff=(bm+1)*256; skip if empty; raw store to part[z].
// ---------------------------------------------------------------------------
template <int MODE>
__global__ void __launch_bounds__(NTHREADS, 1)
tc_ws(const float* A, const float* B, float* C,
      const float* Ay, const float* Bk, float* Ck,
      const float* Bv, float* Cv,
      int M, int N, int K, float scale) {
  int tmode = MODE;
  if (MODE == 4) {
    const int z = blockIdx.z;
    if (z == 0)      { tmode = 0; }
    else if (z == 1) { A = Ay; B = Bk; C = Ck; tmode = 0; }
    else             { A = Ay; B = Bv; C = Cv; tmode = 1; }
  }
  const int bm = blockIdx.y;
  const int bn = blockIdx.x;
  if (MODE == 2 && bn > bm) return;

  int kstart = 0;
  int kend = K;
  if (MODE == 5) {
    const int Keff = min(K, (bm + 1) * BMC);
    kstart = blockIdx.z * KCHUNK;
    kend = min(Keff, kstart + KCHUNK);
    if (kstart >= Keff) return;
    C += (size_t)blockIdx.z * OUT_ELEMS;   // partial buffer for this chunk
  }
  const int row0 = bm * BMC, col0 = bn * BNC;
  const int nT = (kend - kstart) / KT;
  extern __shared__ char smem[];
  const int tid = threadIdx.x;
  const int wid = tid >> 5;

#if USE_TCGEN05
  const uint32_t sb = smem_u32(smem);
  constexpr uint32_t FULL_CNT = (MODE == 4) ? 512u : 256u;

  if (wid == 8) { tmem_alloc(sb, 512); tmem_relinq(); }
  if (tid == 0) {
#pragma unroll
    for (int s = 0; s < SS; ++s) {
      mbar_init(sb + MBAR_OFF + 16 * s, FULL_CNT);      // full[s]
      mbar_init(sb + MBAR_OFF + 16 * s + 8, 1);         // done[s]
    }
  }
  __syncthreads();
  uint32_t tmem;
  asm volatile("ld.shared.b32 %0, [%1];" : "=r"(tmem) : "r"(sb));

  if (tid < 256) {
    // ---------------- producers (warps 0-7): one row of A and B each -------
    const float* Ag = A + (size_t)(row0 + tid) * K + kstart;
    const float* Bg = B + (size_t)(col0 + tid) * K + kstart;
    const int swr = tid * 128;   // byte offset of this row in a 128B-row tile

    for (int t = 0; t < nT; ++t) {
      const int s = t % SS;
      if (t >= SS) mbar_wait(sb + MBAR_OFF + 16 * s + 8, ((t / SS) - 1) & 1);
      const uint32_t base = sb + DATA_OFF + s * STB;

      if (MODE == 4) {
        // A row: LDG -> rna -> STS, FULL 32 floats (128 B)
        const float* ap = Ag + (size_t)t * KT;
        float4 v[8];
#pragma unroll
        for (int i = 0; i < 8; ++i) v[i] = *(const float4*)(ap + i * 4);
        char* d = smem + DATA_OFF + s * STB;
#pragma unroll
        for (int i = 0; i < 8; ++i)
          *(float4*)(d + SWZ(swr + i * 16)) = tf32r4(v[i]);
      } else {
        const float* ap = Ag + (size_t)t * KT;
#pragma unroll
        for (int i = 0; i < 8; ++i)
          cp16(base + SWZ(swr + i * 16), ap + i * 4);
      }
      {
        const float* bp = Bg + (size_t)t * KT;
#pragma unroll
        for (int i = 0; i < 8; ++i)
          cp16(base + ABYTES + SWZ(swr + i * 16), bp + i * 4);
      }
      if (MODE == 4) {
        asm volatile("fence.proxy.async.shared::cta;" ::: "memory");
        mbar_arrive(sb + MBAR_OFF + 16 * s);              // release STS
      }
      cp_arrive_noinc(sb + MBAR_OFF + 16 * s);            // cp completion
    }

    // ---------------- epilogue (warps 0-7) ----------------
    mbar_wait(sb + MBAR_OFF + 16 * ((nT - 1) % SS) + 8, ((nT - 1) / SS) & 1);
    asm volatile("tcgen05.fence::after_thread_sync;" ::: "memory");

    const int wg = tid >> 7, sp = (tid >> 5) & 3, lane = tid & 31;
    uint32_t r[32];
#pragma unroll
    for (int ms = 0; ms < 2; ++ms) {
      const int row = row0 + ms * 128 + sp * 32 + lane;
#pragma unroll
      for (int ch = 0; ch < 4; ++ch) {
        const int colb = wg * 128 + ch * 32;
        ldtm_x32(r, tmem + ms * 256 + colb);
        asm volatile("tcgen05.wait::ld.sync.aligned;" ::: "memory");
        if (tmode == 1) {                 // vT: transposed store
#pragma unroll
          for (int j = 0; j < 32; ++j)
            C[(size_t)(col0 + colb + j) * M + row] =
                tf32r(__uint_as_float(r[j]));
        } else if (tmode == 2) {          // mask + scale
          float* cp = C + (size_t)row * N + col0 + colb;
#pragma unroll
          for (int j = 0; j < 32; ++j) {
            const int c = col0 + colb + j;
            cp[j] = (c >= row) ? 0.0f : tf32r(__uint_as_float(r[j]) * scale);
          }
        } else if (tmode == 0) {          // q/k: tf32-rounded
          float* cp = C + (size_t)row * N + col0 + colb;
#pragma unroll
          for (int j = 0; j < 32; ++j) cp[j] = tf32r(__uint_as_float(r[j]));
        } else {                          // partials: raw f32
          float* cp = C + (size_t)row * N + col0 + colb;
#pragma unroll
          for (int j = 0; j < 32; ++j) cp[j] = __uint_as_float(r[j]);
        }
      }
    }
  } else {
    // ---------------- MMA warp (warp 8) ----------------
    const int lane = tid & 31;
    for (int t = 0; t < nT; ++t) {
      const int s = t % SS;
      mbar_wait(sb + MBAR_OFF + 16 * s, (t / SS) & 1);
      if (lane == 0) {
        asm volatile("fence.proxy.async.shared::cta;" ::: "memory");
        const uint32_t base = sb + DATA_OFF + s * STB;
        const uint64_t bd = DESC_BASE | (((base + ABYTES) >> 4) & 0x3FFF);
#pragma unroll
        for (int ms = 0; ms < 2; ++ms) {
          const uint64_t ad =
              DESC_BASE | (((base + ms * 16384) >> 4) & 0x3FFF);
#pragma unroll
          for (int ks = 0; ks < 4; ++ks)
            mma_tf32(tmem + ms * 256, ad + 2 * ks, bd + 2 * ks, IDESC,
                     (t > 0) || (ks > 0));
        }
        mma_commit(sb + MBAR_OFF + 16 * s + 8);
      }
      __syncwarp();
    }
  }

  __syncthreads();
  if (tid == 0) {
#pragma unroll
    for (int s = 0; s < SS; ++s) {
      mbar_inval(sb + MBAR_OFF + 16 * s);
      mbar_inval(sb + MBAR_OFF + 16 * s + 8);
    }
  }
  if (wid == 8) tmem_dealloc(tmem, 512);

#elif defined(__CUDA_ARCH__)
  (void)smem; (void)nT; (void)wid;
  for (int e = tid; e < BMC * BNC; e += blockDim.x) {
    const int rr = row0 + e / BNC;
    const int cc = col0 + e % BNC;
    float s = 0.f;
    for (int kk = kstart; kk < kend; ++kk)
      s += A[(size_t)rr * K + kk] * B[(size_t)cc * K + kk];
    if (tmode == 2) s = (cc >= rr) ? 0.f : s * scale;
    if (tmode == 1) C[(size_t)cc * M + rr] = s;
    else            C[(size_t)rr * N + cc] = s;
  }
#endif
}

// ---------------------------------------------------------------------------

extern "C" void kernel_launch(void* const* d_in, const int* in_sizes, int n_in,
                              void* d_out, int out_size) {
  (void)in_sizes; (void)n_in; (void)out_size;
  const float* x  = (const float*)d_in[0];
  const float* y  = (const float*)d_in[1];
  const float* Wq = (const float*)d_in[2];
  const float* Wk = (const float*)d_in[3];
  const float* Wv = (const float*)d_in[4];
  float* out = (float*)d_out;

  float *wqc, *wkc, *wvc, *q, *k, *vT, *a, *part;
  cudaGetSymbolAddress((void**)&wqc, g_wqc);
  cudaGetSymbolAddress((void**)&wkc, g_wkc);
  cudaGetSymbolAddress((void**)&wvc, g_wvc);
  cudaGetSymbolAddress((void**)&q, g_q);
  cudaGetSymbolAddress((void**)&k, g_k);
  cudaGetSymbolAddress((void**)&vT, g_vT);
  cudaGetSymbolAddress((void**)&a, g_a);
  cudaGetSymbolAddress((void**)&part, g_part);

  cudaFuncSetAttribute(tc_ws<2>, cudaFuncAttributeMaxDynamicSharedMemorySize,
                       SMEM_SZ);
  cudaFuncSetAttribute(tc_ws<4>, cudaFuncAttributeMaxDynamicSharedMemorySize,
                       SMEM_SZ);
  cudaFuncSetAttribute(tc_ws<5>, cudaFuncAttributeMaxDynamicSharedMemorySize,
                       SMEM_SZ);

  dim3 blk(NTHREADS, 1, 1);
  const float scale = 1.0f / sqrtf((float)kD);

  // Stage 0: RNE-convert weights (12 MB)
  cvt_kernel<<<dim3(64, 1, 3), dim3(256, 1, 1)>>>(Wq, wqc, Wk, wkc, Wv, wvc,
                                                  kD * kC);

  // Stage 1: fused projections q, k, vT (x/y converted in-producer)
  tc_ws<4><<<dim3(kD / BNC, kNX / BMC, 3), blk, SMEM_SZ>>>(
      x, wqc, q, y, wkc, k, wvc, vT, kNX, kD, kC, 1.0f);

  // Stage 2: a = mask(q k^T)*scale (256x256 blocks, skip bn>bm)
  tc_ws<2><<<dim3(kNY / BNC, kNX / BMC), blk, SMEM_SZ>>>(
      q, k, a, nullptr, nullptr, nullptr, nullptr, nullptr,
      kNX, kNY, kD, scale);

  // Stage 3: split-K partials (chunks of 2048), then fixed-order reduce
  tc_ws<5><<<dim3(kD / BNC, kNX / BMC, kNY / KCHUNK), blk, SMEM_SZ>>>(
      a, vT, part, nullptr, nullptr, nullptr, nullptr, nullptr,
      kNX, kD, kNY, 1.0f);
  reduce_kernel<<<(int)(OUT_ELEMS / 4 + 255) / 256, 256>>>(part, out);
}

// round 15
// speedup vs baseline: 1.4889x; 1.4889x over previous
#include <cuda_runtime.h>
#include <cstdint>
#include <cmath>

// ---------------------------------------------------------------------------
// Head_55671366091048 (sm_103a), warp-specialized tcgen05, 256x256 tiles.
//   Wc = rna(W)
//   q = rna(x) Wqc^T ; k = rna(y) Wkc^T ; vT = (rna(y) Wvc^T)^T  (fused z=3)
//   a = mask(q k^T) * d^-1/2    (strict lower; 256x256 blocks, skip bn>bm)
//   part[c] = a[:, c*2048:(c+1)*2048] vT^T  (split-K, 160 balanced CTAs)
//   out = sum_c part[c]                      (fixed-order reduce)
//
// Round-14 lesson: 1-thread-per-row producers cost 32 L1tex wavefronts per
// cp.async warp-instruction (~4096 cyc/tile). This round restores the
// 8-threads-per-row mapping (4 lines/instruction): r0=tid>>3, c16=tid&7,
// rows r0+32i. Everything else identical to the passing round-14 kernel.
// ---------------------------------------------------------------------------

#if defined(__CUDA_ARCH__) && defined(__CUDA_ARCH_FEAT_SM103_ALL)
#define USE_TCGEN05 1
#else
#define USE_TCGEN05 0
#endif

namespace {
constexpr int kNX = 8192;
constexpr int kNY = 8192;
constexpr int kC  = 2048;
constexpr int kD  = 512;

constexpr int BMC = 256;                 // CTA rows (2 x 128 MMA m-blocks)
constexpr int BNC = 256;                 // CTA cols
constexpr int KT  = 32;                  // K per smem tile (128B rows)
constexpr int SS  = 3;                   // stages
constexpr int ABYTES = BMC * 128;        // 32 KB
constexpr int BBYTES = BNC * 128;        // 32 KB
constexpr int STB = ABYTES + BBYTES;     // 64 KB
constexpr int MBAR_OFF = 64;             // full[s] @ +16s, done[s] @ +16s+8
constexpr int DATA_OFF = 1024;
constexpr int SMEM_SZ = DATA_OFF + SS * STB;   // 197632 B -> 1 CTA/SM

constexpr int NTHREADS = 288;            // 8 producer warps + 1 MMA warp
constexpr int KCHUNK = 2048;             // split-K chunk (stage 3)
constexpr size_t OUT_ELEMS = (size_t)kNX * kD;

constexpr uint64_t DESC_BASE =
    (uint64_t(2) << 61) | (uint64_t(1) << 46) | (uint64_t(64) << 32) |
    (uint64_t(1) << 16);

// idesc kind::tf32: dtype F32, a/b TF32, N=256, M=128 per dispatch
constexpr uint32_t IDESC =
    (1u << 4) | (2u << 7) | (2u << 10) | ((BNC / 8) << 17) | (8u << 24);
}  // namespace

__device__ float g_wqc[(size_t)kD * kC];
__device__ float g_wkc[(size_t)kD * kC];
__device__ float g_wvc[(size_t)kD * kC];
__device__ float g_q[(size_t)kNX * kD];
__device__ float g_k[(size_t)kNY * kD];
__device__ float g_vT[(size_t)kD * kNY];
__device__ float g_a[(size_t)kNX * kNY];
__device__ float g_part[4][OUT_ELEMS];   // split-K partials

// ---------------------------------------------------------------------------
__device__ __forceinline__ uint32_t smem_u32(const void* p) {
  uint32_t a;
  asm("{ .reg .u64 t; cvta.to.shared.u64 t, %1; cvt.u32.u64 %0, t; }"
      : "=r"(a) : "l"(p));
  return a;
}
__device__ __forceinline__ float tf32r(float f) {
  uint32_t u;
  asm("cvt.rna.tf32.f32 %0, %1;" : "=r"(u) : "f"(f));
  return __uint_as_float(u);
}
__device__ __forceinline__ float4 tf32r4(float4 v) {
  return make_float4(tf32r(v.x), tf32r(v.y), tf32r(v.z), tf32r(v.w));
}

__global__ void cvt_kernel(const float* s0, float* d0, const float* s1,
                           float* d1, const float* s2, float* d2, int n) {
  const int z = blockIdx.z;
  const float* s = (z == 0) ? s0 : (z == 1) ? s1 : s2;
  float* d = (z == 0) ? d0 : (z == 1) ? d1 : d2;
  int i = (blockIdx.x * blockDim.x + threadIdx.x) * 4;
  const int stride = gridDim.x * blockDim.x * 4;
  for (; i < n; i += stride) *(float4*)(d + i) = tf32r4(*(const float4*)(s + i));
}

// out = sum over valid chunks of part[c]; nch(row) = row/2048 + 1 (1..4)
__global__ void reduce_kernel(const float* __restrict__ part,
                              float* __restrict__ out) {
  const size_t i4 = ((size_t)blockIdx.x * blockDim.x + threadIdx.x) * 4;
  if (i4 >= OUT_ELEMS) return;
  const int row = (int)(i4 / kD);
  const int nch = row / KCHUNK + 1;
  float4 s = *(const float4*)(part + i4);
  for (int c = 1; c < nch; ++c) {
    const float4 p = *(const float4*)(part + (size_t)c * OUT_ELEMS + i4);
    s.x += p.x; s.y += p.y; s.z += p.z; s.w += p.w;
  }
  *(float4*)(out + i4) = s;
}

#if USE_TCGEN05
__device__ __forceinline__ void mbar_init(uint32_t addr, uint32_t cnt) {
  asm volatile("mbarrier.init.shared.b64 [%0], %1;" :: "r"(addr), "r"(cnt)
               : "memory");
}
__device__ __forceinline__ void mbar_inval(uint32_t addr) {
  asm volatile("mbarrier.inval.shared.b64 [%0];" :: "r"(addr) : "memory");
}
__device__ __forceinline__ void mbar_arrive(uint32_t addr) {
  asm volatile("mbarrier.arrive.shared.b64 _, [%0];" :: "r"(addr) : "memory");
}
__device__ __forceinline__ void mbar_wait(uint32_t addr, uint32_t parity) {
  uint32_t done;
  asm volatile(
      "{\n\t.reg .pred p;\n\t"
      "mbarrier.try_wait.parity.acquire.cta.shared::cta.b64 p, [%1], %2;\n\t"
      "selp.b32 %0, 1, 0, p;\n\t}"
      : "=r"(done) : "r"(addr), "r"(parity) : "memory");
  if (!done) {
    asm volatile(
        "{\n\t.reg .pred P1;\n\t"
        "WL_%=:\n\t"
        "mbarrier.try_wait.parity.acquire.cta.shared::cta.b64 P1, [%0], %1, 0x989680;\n\t"
        "@P1 bra.uni WD_%=;\n\t"
        "bra.uni WL_%=;\n\t"
        "WD_%=:\n\t}"
        :: "r"(addr), "r"(parity) : "memory");
  }
}
__device__ __forceinline__ void tmem_alloc(uint32_t smem_dst, uint32_t ncols) {
  asm volatile(
      "tcgen05.alloc.cta_group::1.sync.aligned.shared::cta.b32 [%0], %1;"
      :: "r"(smem_dst), "r"(ncols) : "memory");
}
__device__ __forceinline__ void tmem_relinq() {
  asm volatile("tcgen05.relinquish_alloc_permit.cta_group::1.sync.aligned;");
}
__device__ __forceinline__ void tmem_dealloc(uint32_t tmem, uint32_t ncols) {
  asm volatile("tcgen05.dealloc.cta_group::1.sync.aligned.b32 %0, %1;"
               :: "r"(tmem), "r"(ncols));
}
__device__ __forceinline__ void mma_tf32(uint32_t d, uint64_t ad, uint64_t bd,
                                         uint32_t idesc, bool accum) {
  uint32_t en = accum ? 1u : 0u;
  asm volatile(
      "{\n\t.reg .pred p;\n\t"
      "setp.ne.u32 p, %4, 0;\n\t"
      "tcgen05.mma.cta_group::1.kind::tf32 [%0], %1, %2, %3, {%5,%5,%5,%5}, p;\n\t}"
      :: "r"(d), "l"(ad), "l"(bd), "r"(idesc), "r"(en), "r"(0u) : "memory");
}
__device__ __forceinline__ void mma_commit(uint32_t mbar) {
  asm volatile(
      "tcgen05.commit.cta_group::1.mbarrier::arrive::one.shared::cluster.b64 [%0];"
      :: "r"(mbar) : "memory");
}
__device__ __forceinline__ void ldtm_x32(uint32_t* r, uint32_t addr) {
  asm volatile(
      "tcgen05.ld.sync.aligned.32x32b.x32.b32 "
      "{%0,%1,%2,%3,%4,%5,%6,%7,%8,%9,%10,%11,%12,%13,%14,%15,"
      "%16,%17,%18,%19,%20,%21,%22,%23,%24,%25,%26,%27,%28,%29,%30,%31}, [%32];"
      : "=r"(r[0]), "=r"(r[1]), "=r"(r[2]), "=r"(r[3]), "=r"(r[4]), "=r"(r[5]),
        "=r"(r[6]), "=r"(r[7]), "=r"(r[8]), "=r"(r[9]), "=r"(r[10]),
        "=r"(r[11]), "=r"(r[12]), "=r"(r[13]), "=r"(r[14]), "=r"(r[15]),
        "=r"(r[16]), "=r"(r[17]), "=r"(r[18]), "=r"(r[19]), "=r"(r[20]),
        "=r"(r[21]), "=r"(r[22]), "=r"(r[23]), "=r"(r[24]), "=r"(r[25]),
        "=r"(r[26]), "=r"(r[27]), "=r"(r[28]), "=r"(r[29]), "=r"(r[30]),
        "=r"(r[31])
      : "r"(addr));
}
__device__ __forceinline__ void cp16(uint32_t dst, const void* src) {
  asm volatile("cp.async.cg.shared.global [%0], [%1], 16;"
               :: "r"(dst), "l"(src) : "memory");
}
__device__ __forceinline__ void cp_arrive_noinc(uint32_t mbar) {
  asm volatile("cp.async.mbarrier.arrive.noinc.shared.b64 [%0];"
               :: "r"(mbar) : "memory");
}
#endif  // USE_TCGEN05

#define SWZ(o) ((o) ^ (((o) >> 3) & 0x70))

// ---------------------------------------------------------------------------
// Warp-specialized NT GEMM, 256x256 CTA tile, TMEM 512 cols.
// Producer mapping (coalesced): r0=tid>>3 (0..31), c16=tid&7; thread covers
// rows r0+32i (i=0..7), 16B chunk c16 -> 4 lines per warp instruction.
// MODE 2: skip bn>bm (256-blocks); mask+scale epilogue (tf32-rounded).
// MODE 4: fused projections; A in-producer (LDG->rna->STS); z=0 q, z=1 k,
//         z=2 vT (transposed store), tf32-rounded.
// MODE 5: stage-3 split-K: chunk z covers K [z*2048, min(Keff,(z+1)*2048));
//         Keff=(bm+1)*256; skip if empty; raw store to part[z].
// ---------------------------------------------------------------------------
template <int MODE>
__global__ void __launch_bounds__(NTHREADS, 1)
tc_ws(const float* A, const float* B, float* C,
      const float* Ay, const float* Bk, float* Ck,
      const float* Bv, float* Cv,
      int M, int N, int K, float scale) {
  int tmode = MODE;
  if (MODE == 4) {
    const int z = blockIdx.z;
    if (z == 0)      { tmode = 0; }
    else if (z == 1) { A = Ay; B = Bk; C = Ck; tmode = 0; }
    else             { A = Ay; B = Bv; C = Cv; tmode = 1; }
  }
  const int bm = blockIdx.y;
  const int bn = blockIdx.x;
  if (MODE == 2 && bn > bm) return;

  int kstart = 0;
  int kend = K;
  if (MODE == 5) {
    const int Keff = min(K, (bm + 1) * BMC);
    kstart = blockIdx.z * KCHUNK;
    kend = min(Keff, kstart + KCHUNK);
    if (kstart >= Keff) return;
    C += (size_t)blockIdx.z * OUT_ELEMS;   // partial buffer for this chunk
  }
  const int row0 = bm * BMC, col0 = bn * BNC;
  const int nT = (kend - kstart) / KT;
  extern __shared__ char smem[];
  const int tid = threadIdx.x;
  const int wid = tid >> 5;

#if USE_TCGEN05
  const uint32_t sb = smem_u32(smem);
  constexpr uint32_t FULL_CNT = (MODE == 4) ? 512u : 256u;

  if (wid == 8) { tmem_alloc(sb, 512); tmem_relinq(); }
  if (tid == 0) {
#pragma unroll
    for (int s = 0; s < SS; ++s) {
      mbar_init(sb + MBAR_OFF + 16 * s, FULL_CNT);      // full[s]
      mbar_init(sb + MBAR_OFF + 16 * s + 8, 1);         // done[s]
    }
  }
  __syncthreads();
  uint32_t tmem;
  asm volatile("ld.shared.b32 %0, [%1];" : "=r"(tmem) : "r"(sb));

  if (tid < 256) {
    // -------- producers (warps 0-7): coalesced 8-threads-per-row map ------
    const int r0  = tid >> 3;          // 0..31
    const int c16 = tid & 7;           // 16B chunk in row
    const float* Ag = A + (size_t)(row0 + r0) * K + kstart + c16 * 4;
    const float* Bg = B + (size_t)(col0 + r0) * K + kstart + c16 * 4;
    const size_t rstep = (size_t)32 * K;            // 32 rows
    const int swb = SWZ(r0 * 128 + c16 * 16);       // +32 rows keeps bits[9:7]

    for (int t = 0; t < nT; ++t) {
      const int s = t % SS;
      if (t >= SS) mbar_wait(sb + MBAR_OFF + 16 * s + 8, ((t / SS) - 1) & 1);
      const uint32_t base = sb + DATA_OFF + s * STB;

      if (MODE == 4) {
        // A rows: LDG -> rna -> STS (one float4 per row, 8 rows)
        const float* ap = Ag + (size_t)t * KT;
        float4 v[8];
#pragma unroll
        for (int i = 0; i < 8; ++i) v[i] = *(const float4*)(ap + i * rstep);
        char* d = smem + DATA_OFF + s * STB + swb;
#pragma unroll
        for (int i = 0; i < 8; ++i)
          *(float4*)(d + i * 4096) = tf32r4(v[i]);
      } else {
        const float* ap = Ag + (size_t)t * KT;
#pragma unroll
        for (int i = 0; i < 8; ++i)
          cp16(base + swb + i * 4096, ap + i * rstep);
      }
      {
        const float* bp = Bg + (size_t)t * KT;
#pragma unroll
        for (int i = 0; i < 8; ++i)
          cp16(base + ABYTES + swb + i * 4096, bp + i * rstep);
      }
      if (MODE == 4) {
        asm volatile("fence.proxy.async.shared::cta;" ::: "memory");
        mbar_arrive(sb + MBAR_OFF + 16 * s);              // release STS
      }
      cp_arrive_noinc(sb + MBAR_OFF + 16 * s);            // cp completion
    }

    // ---------------- epilogue (warps 0-7) ----------------
    mbar_wait(sb + MBAR_OFF + 16 * ((nT - 1) % SS) + 8, ((nT - 1) / SS) & 1);
    asm volatile("tcgen05.fence::after_thread_sync;" ::: "memory");

    const int wg = tid >> 7, sp = (tid >> 5) & 3, lane = tid & 31;
    uint32_t r[32];
#pragma unroll
    for (int ms = 0; ms < 2; ++ms) {
      const int row = row0 + ms * 128 + sp * 32 + lane;
#pragma unroll
      for (int ch = 0; ch < 4; ++ch) {
        const int colb = wg * 128 + ch * 32;
        ldtm_x32(r, tmem + ms * 256 + colb);
        asm volatile("tcgen05.wait::ld.sync.aligned;" ::: "memory");
        if (tmode == 1) {                 // vT: transposed store
#pragma unroll
          for (int j = 0; j < 32; ++j)
            C[(size_t)(col0 + colb + j) * M + row] =
                tf32r(__uint_as_float(r[j]));
        } else if (tmode == 2) {          // mask + scale
          float* cp = C + (size_t)row * N + col0 + colb;
#pragma unroll
          for (int j = 0; j < 32; ++j) {
            const int c = col0 + colb + j;
            cp[j] = (c >= row) ? 0.0f : tf32r(__uint_as_float(r[j]) * scale);
          }
        } else if (tmode == 0) {          // q/k: tf32-rounded
          float* cp = C + (size_t)row * N + col0 + colb;
#pragma unroll
          for (int j = 0; j < 32; ++j) cp[j] = tf32r(__uint_as_float(r[j]));
        } else {                          // partials: raw f32
          float* cp = C + (size_t)row * N + col0 + colb;
#pragma unroll
          for (int j = 0; j < 32; ++j) cp[j] = __uint_as_float(r[j]);
        }
      }
    }
  } else {
    // ---------------- MMA warp (warp 8) ----------------
    const int lane = tid & 31;
    for (int t = 0; t < nT; ++t) {
      const int s = t % SS;
      mbar_wait(sb + MBAR_OFF + 16 * s, (t / SS) & 1);
      if (lane == 0) {
        asm volatile("fence.proxy.async.shared::cta;" ::: "memory");
        const uint32_t base = sb + DATA_OFF + s * STB;
        const uint64_t bd = DESC_BASE | (((base + ABYTES) >> 4) & 0x3FFF);
#pragma unroll
        for (int ms = 0; ms < 2; ++ms) {
          const uint64_t ad =
              DESC_BASE | (((base + ms * 16384) >> 4) & 0x3FFF);
#pragma unroll
          for (int ks = 0; ks < 4; ++ks)
            mma_tf32(tmem + ms * 256, ad + 2 * ks, bd + 2 * ks, IDESC,
                     (t > 0) || (ks > 0));
        }
        mma_commit(sb + MBAR_OFF + 16 * s + 8);
      }
      __syncwarp();
    }
  }

  __syncthreads();
  if (tid == 0) {
#pragma unroll
    for (int s = 0; s < SS; ++s) {
      mbar_inval(sb + MBAR_OFF + 16 * s);
      mbar_inval(sb + MBAR_OFF + 16 * s + 8);
    }
  }
  if (wid == 8) tmem_dealloc(tmem, 512);

#elif defined(__CUDA_ARCH__)
  (void)smem; (void)nT; (void)wid;
  for (int e = tid; e < BMC * BNC; e += blockDim.x) {
    const int rr = row0 + e / BNC;
    const int cc = col0 + e % BNC;
    float s = 0.f;
    for (int kk = kstart; kk < kend; ++kk)
      s += A[(size_t)rr * K + kk] * B[(size_t)cc * K + kk];
    if (tmode == 2) s = (cc >= rr) ? 0.f : s * scale;
    if (tmode == 1) C[(size_t)cc * M + rr] = s;
    else            C[(size_t)rr * N + cc] = s;
  }
#endif
}

// ---------------------------------------------------------------------------

extern "C" void kernel_launch(void* const* d_in, const int* in_sizes, int n_in,
                              void* d_out, int out_size) {
  (void)in_sizes; (void)n_in; (void)out_size;
  const float* x  = (const float*)d_in[0];
  const float* y  = (const float*)d_in[1];
  const float* Wq = (const float*)d_in[2];
  const float* Wk = (const float*)d_in[3];
  const float* Wv = (const float*)d_in[4];
  float* out = (float*)d_out;

  float *wqc, *wkc, *wvc, *q, *k, *vT, *a, *part;
  cudaGetSymbolAddress((void**)&wqc, g_wqc);
  cudaGetSymbolAddress((void**)&wkc, g_wkc);
  cudaGetSymbolAddress((void**)&wvc, g_wvc);
  cudaGetSymbolAddress((void**)&q, g_q);
  cudaGetSymbolAddress((void**)&k, g_k);
  cudaGetSymbolAddress((void**)&vT, g_vT);
  cudaGetSymbolAddress((void**)&a, g_a);
  cudaGetSymbolAddress((void**)&part, g_part);

  cudaFuncSetAttribute(tc_ws<2>, cudaFuncAttributeMaxDynamicSharedMemorySize,
                       SMEM_SZ);
  cudaFuncSetAttribute(tc_ws<4>, cudaFuncAttributeMaxDynamicSharedMemorySize,
                       SMEM_SZ);
  cudaFuncSetAttribute(tc_ws<5>, cudaFuncAttributeMaxDynamicSharedMemorySize,
                       SMEM_SZ);

  dim3 blk(NTHREADS, 1, 1);
  const float scale = 1.0f / sqrtf((float)kD);

  // Stage 0: RNE-convert weights (12 MB)
  cvt_kernel<<<dim3(64, 1, 3), dim3(256, 1, 1)>>>(Wq, wqc, Wk, wkc, Wv, wvc,
                                                  kD * kC);

  // Stage 1: fused projections q, k, vT (x/y converted in-producer)
  tc_ws<4><<<dim3(kD / BNC, kNX / BMC, 3), blk, SMEM_SZ>>>(
      x, wqc, q, y, wkc, k, wvc, vT, kNX, kD, kC, 1.0f);

  // Stage 2: a = mask(q k^T)*scale (256x256 blocks, skip bn>bm)
  tc_ws<2><<<dim3(kNY / BNC, kNX / BMC), blk, SMEM_SZ>>>(
      q, k, a, nullptr, nullptr, nullptr, nullptr, nullptr,
      kNX, kNY, kD, scale);

  // Stage 3: split-K partials (chunks of 2048), then fixed-order reduce
  tc_ws<5><<<dim3(kD / BNC, kNX / BMC, kNY / KCHUNK), blk, SMEM_SZ>>>(
      a, vT, part, nullptr, nullptr, nullptr, nullptr, nullptr,
      kNX, kD, kNY, 1.0f);
  reduce_kernel<<<(int)(OUT_ELEMS / 4 + 255) / 256, 256>>>(part, out);
}